// round 15
// baseline (speedup 1.0000x reference)
#include <cuda_runtime.h>
#include <cuda_fp16.h>
#include <math.h>
#include <stdio.h>

// ---------------- problem constants ----------------
constexpr int D_   = 128;   // in dim
constexpr int H_   = 4;     // heads
constexpr int C_   = 128;   // channels per head
constexpr int HC   = 512;   // H*C
constexpr int B_   = 64;    // graphs
constexpr int NMAX = 50000;
constexpr int EMAX = 400000;
constexpr int TMAX = NMAX + EMAX;  // edges + self loops
constexpr float NEG_SLOPE = 0.2f;
constexpr float EPS_ = 1e-5f;

// ---------------- scratch (static device globals; no allocation) -------------
// Referenced ONLY from device code (GB300 ATS silently accepts host-shadow
// addresses passed as kernel args — round-4 bug).
__device__ float  g_h   [(size_t)NMAX * D_];      // fp32 residual stream
__device__ __half g_h16 [(size_t)NMAX * D_];      // fp16 mirror (GEMM A input)
__device__ __half g_xl_h[(size_t)NMAX * HC];      // fp16 projections (L2-resident)
__device__ __half g_xr_h[(size_t)NMAX * HC];
__device__ int    g_src[TMAX];
__device__ int    g_dst[TMAX];
__device__ int    g_deg[NMAX];
__device__ int    g_rowptr[NMAX + 1];
__device__ int    g_cursor[NMAX];
__device__ int    g_csrs[TMAX];                   // CSR: src id per slot
__device__ int    g_batch[NMAX];
__device__ int    g_flag[2];
__device__ float  g_pool[B_ * C_];

// ---------------- small utility kernels ----------------
__global__ void zero_flags_deg(int N) {
    int i = blockIdx.x * blockDim.x + threadIdx.x;
    if (i < 2) g_flag[i] = 0;
    if (i < N) g_deg[i] = 0;
}
__global__ void sniff_kernel(const int* __restrict__ buf, int npairs, int which) {
    int i = blockIdx.x * blockDim.x + threadIdx.x;
    if (i < npairs && buf[2 * i + 1] != 0) g_flag[which] = 1;
}
__device__ __forceinline__ int clampi(int v, int lo, int hi) {
    return v < lo ? lo : (v > hi ? hi : v);
}
// converts edges AND counts in-degrees
__global__ void convert_edges(const int* __restrict__ buf, int E, int N, int forced) {
    int i = blockIdx.x * blockDim.x + threadIdx.x;
    if (i >= E) return;
    int is32 = (forced >= 0) ? forced : g_flag[0];
    int s, d;
    if (is32) { s = buf[i];     d = buf[E + i]; }
    else      { s = buf[2 * i]; d = buf[2 * (E + i)]; }
    s = clampi(s, 0, N - 1);
    d = clampi(d, 0, N - 1);
    g_src[i] = s;
    g_dst[i] = d;
    atomicAdd(&g_deg[d], 1);
}
__global__ void fill_selfloops(int N, int E) {
    int i = blockIdx.x * blockDim.x + threadIdx.x;
    if (i >= N) return;
    g_src[E + i] = i;
    g_dst[E + i] = i;
    g_deg[i] += 1;
}
__global__ void convert_batch(const int* __restrict__ buf, int N, int forced) {
    int i = blockIdx.x * blockDim.x + threadIdx.x;
    if (i >= N) return;
    int is32 = (forced >= 0) ? forced : g_flag[1];
    int b = is32 ? buf[i] : buf[2 * i];
    g_batch[i] = clampi(b, 0, B_ - 1);
}
// copies x into g_h (fp32) and g_h16 (fp16)
__global__ void copy_x(const float4* __restrict__ x4, int n4) {
    int i = blockIdx.x * blockDim.x + threadIdx.x;
    if (i >= n4) return;
    float4 v = x4[i];
    ((float4*)g_h)[i] = v;
    __half2 h0 = __floats2half2_rn(v.x, v.y);
    __half2 h1 = __floats2half2_rn(v.z, v.w);
    ((uint2*)g_h16)[i] = make_uint2(*(unsigned*)&h0, *(unsigned*)&h1);
}
__global__ void scan_kernel(int N) {
    __shared__ int sh[1024];
    __shared__ int carry_s;
    int tid = threadIdx.x;
    if (tid == 0) carry_s = 0;
    __syncthreads();
    for (int base = 0; base < N; base += 1024) {
        int v = (base + tid < N) ? g_deg[base + tid] : 0;
        sh[tid] = v;
        __syncthreads();
        for (int off = 1; off < 1024; off <<= 1) {
            int t = (tid >= off) ? sh[tid - off] : 0;
            __syncthreads();
            sh[tid] += t;
            __syncthreads();
        }
        int excl = sh[tid] - v + carry_s;
        if (base + tid < N) { g_rowptr[base + tid] = excl; g_cursor[base + tid] = excl; }
        __syncthreads();
        if (tid == 0) carry_s += sh[1023];
        __syncthreads();
    }
    if (tid == 0) g_rowptr[N] = carry_s;
}
__global__ void scatter_csr(int T) {
    int i = blockIdx.x * blockDim.x + threadIdx.x;
    if (i >= T) return;
    int d = g_dst[i];
    int pos = atomicAdd(&g_cursor[d], 1);
    if (pos < TMAX) g_csrs[pos] = g_src[i];
}

// ---------------- tensor-core GEMM (fp16 m16n8k16, fp32 accum) --------------
// Fused xl+xr: blockIdx.z selects (Wl->g_xl_h) or (Wr->g_xr_h).
// Block tile: 128 nodes x 64 cols. K=128 in TWO chunks of 64 halves
// (= 32 uints per row, pitch 36 -> all indices < 36, conflict-free frags).
__device__ __forceinline__ void mma_f16(float* c, const unsigned* a,
                                        unsigned b0, unsigned b1) {
    asm volatile(
        "mma.sync.aligned.m16n8k16.row.col.f32.f16.f16.f32 "
        "{%0,%1,%2,%3}, {%4,%5,%6,%7}, {%8,%9}, {%0,%1,%2,%3};"
        : "+f"(c[0]), "+f"(c[1]), "+f"(c[2]), "+f"(c[3])
        : "r"(a[0]), "r"(a[1]), "r"(a[2]), "r"(a[3]), "r"(b0), "r"(b1));
}

__global__ __launch_bounds__(256) void gemm_tc(
    const float* __restrict__ Wl, const float* __restrict__ bl,
    const float* __restrict__ Wr, const float* __restrict__ br,
    int N)
{
    int which = blockIdx.z;
    const float* W    = which ? Wr : Wl;
    const float* bias = which ? br : bl;
    __half* out_h     = which ? g_xr_h : g_xl_h;
    const float4* W4 = (const float4*)W;

    __shared__ unsigned Asu[128 * 36];   // chunk: 128 rows x 32 uints(64 halves) + pad
    __shared__ unsigned Bsu[64 * 36];    // chunk: 64 rows x 32 uints(64 halves) + pad

    int tid  = threadIdx.x;
    int warp = tid >> 5;
    int lane = tid & 31;
    int g  = lane >> 2;
    int tg = lane & 3;
    int nb = blockIdx.x * 64;    // col base
    int mb = blockIdx.y * 128;   // node base

    float c[8][4];
#pragma unroll
    for (int i = 0; i < 8; i++)
#pragma unroll
        for (int j = 0; j < 4; j++) c[i][j] = 0.f;

    for (int kc = 0; kc < 128; kc += 64) {
        // A chunk: 128 rows x 8 uint4 (64 halves per row)
#pragma unroll
        for (int it = 0; it < 4; it++) {
            int idx = tid + it * 256;            // 0..1023
            int row = idx >> 3, c4 = idx & 7;    // c4: 0..7
            int rg = mb + row; if (rg > N - 1) rg = N - 1;
            uint4 u = ((const uint4*)(g_h16 + (size_t)rg * 128 + kc))[c4];
            *(uint4*)&Asu[row * 36 + c4 * 4] = u;   // max 31 < 36
        }
        // W chunk: 64 rows x 16 float4 (64 floats per row), fp32 -> fp16
#pragma unroll
        for (int it = 0; it < 4; it++) {
            int idx = tid + it * 256;            // 0..1023
            int row = idx >> 4, c4 = idx & 15;   // c4: 0..15
            float4 f = W4[(size_t)(nb + row) * 32 + kc / 4 + c4];
            __half2 h0 = __floats2half2_rn(f.x, f.y);
            __half2 h1 = __floats2half2_rn(f.z, f.w);
            *(uint2*)&Bsu[row * 36 + c4 * 2] =      // max 31 < 36
                make_uint2(*(unsigned*)&h0, *(unsigned*)&h1);
        }
        __syncthreads();
#pragma unroll
        for (int ks = 0; ks < 4; ks++) {
            int kh = ks * 8;                     // uint offset within chunk row
            unsigned a[4];
            a[0] = Asu[(16 * warp + g) * 36 + kh + tg];
            a[1] = Asu[(16 * warp + g + 8) * 36 + kh + tg];
            a[2] = Asu[(16 * warp + g) * 36 + kh + tg + 4];
            a[3] = Asu[(16 * warp + g + 8) * 36 + kh + tg + 4];
#pragma unroll
            for (int nf = 0; nf < 8; nf++) {
                unsigned b0 = Bsu[(nf * 8 + g) * 36 + kh + tg];
                unsigned b1 = Bsu[(nf * 8 + g) * 36 + kh + tg + 4];
                mma_f16(c[nf], a, b0, b1);
            }
        }
        __syncthreads();
    }

    int node0 = mb + 16 * warp + g;
    int node1 = node0 + 8;
#pragma unroll
    for (int nf = 0; nf < 8; nf++) {
        int col = nb + nf * 8 + 2 * tg;
        float bv0 = __ldg(bias + col), bv1 = __ldg(bias + col + 1);
        if (node0 < N)
            *(__half2*)(out_h + (size_t)node0 * HC + col) =
                __floats2half2_rn(c[nf][0] + bv0, c[nf][1] + bv1);
        if (node1 < N)
            *(__half2*)(out_h + (size_t)node1 * HC + col) =
                __floats2half2_rn(c[nf][2] + bv0, c[nf][3] + bv1);
    }
}

// ---------- fused GAT layer: softmax + aggregate + head-mean/LN/residual -----
// Block = node (128 threads), warp = head. 16-lane-per-edge layout: each lane
// loads uint4 (8 channels); lane halves process 2 edges simultaneously, so the
// 4-deep shfl reduction is shared by 2 edges. 2-pair unroll = 4 edges in flight.
__device__ __forceinline__ float lrelu(float x) { return x > 0.f ? x : NEG_SLOPE * x; }

__device__ __forceinline__ float edge_dot8(const __half* base, size_t srow,
                                           int sub, const float* xr8,
                                           const float* a8, float* v8) {
    uint4 u = ((const uint4*)(base + srow))[sub];
    float2 f0 = __half22float2(*(__half2*)&u.x);
    float2 f1 = __half22float2(*(__half2*)&u.y);
    float2 f2 = __half22float2(*(__half2*)&u.z);
    float2 f3 = __half22float2(*(__half2*)&u.w);
    v8[0] = f0.x; v8[1] = f0.y; v8[2] = f1.x; v8[3] = f1.y;
    v8[4] = f2.x; v8[5] = f2.y; v8[6] = f3.x; v8[7] = f3.y;
    float s = 0.f;
#pragma unroll
    for (int k = 0; k < 8; k++) s = fmaf(lrelu(v8[k] + xr8[k]), a8[k], s);
    return s;
}

__global__ __launch_bounds__(128) void gat_layer(
    const float* __restrict__ att_l, const float* __restrict__ cb,
    const float* __restrict__ gam, const float* __restrict__ bet, int N)
{
    int n = blockIdx.x;
    int h = threadIdx.x >> 5;
    int lane = threadIdx.x & 31;
    int half = lane >> 4;        // 0 or 1: which edge of the pair
    int sub  = lane & 15;        // channel group: channels sub*8 .. sub*8+7

    // xr[n][h] channels sub*8..+7 and att, resident in regs
    float xr8[8], a8[8];
    {
        uint4 u = ((const uint4*)(g_xr_h + (size_t)n * HC + h * C_))[sub];
        float2 f0 = __half22float2(*(__half2*)&u.x);
        float2 f1 = __half22float2(*(__half2*)&u.y);
        float2 f2 = __half22float2(*(__half2*)&u.z);
        float2 f3 = __half22float2(*(__half2*)&u.w);
        xr8[0] = f0.x; xr8[1] = f0.y; xr8[2] = f1.x; xr8[3] = f1.y;
        xr8[4] = f2.x; xr8[5] = f2.y; xr8[6] = f3.x; xr8[7] = f3.y;
        float4 q0 = ((const float4*)(att_l + h * C_ + sub * 8))[0];
        float4 q1 = ((const float4*)(att_l + h * C_ + sub * 8))[1];
        a8[0] = q0.x; a8[1] = q0.y; a8[2] = q0.z; a8[3] = q0.w;
        a8[4] = q1.x; a8[5] = q1.y; a8[6] = q1.z; a8[7] = q1.w;
    }

    int jb = g_rowptr[n], je = g_rowptr[n + 1];

    float denom = 0.f;
    float acc[8];
#pragma unroll
    for (int k = 0; k < 8; k++) acc[k] = 0.f;

    int j = jb;
    // unrolled: 2 pairs = 4 edges, all valid
    for (; j + 4 <= je; j += 4) {
        int sA = g_csrs[j + half];
        int sB = g_csrs[j + 2 + half];
        float vA[8], vB[8];
        float sumA = edge_dot8(g_xl_h, (size_t)sA * HC + h * C_, sub, xr8, a8, vA);
        float sumB = edge_dot8(g_xl_h, (size_t)sB * HC + h * C_, sub, xr8, a8, vB);
#pragma unroll
        for (int o = 8; o > 0; o >>= 1) {
            sumA += __shfl_xor_sync(0xffffffffu, sumA, o);
            sumB += __shfl_xor_sync(0xffffffffu, sumB, o);
        }
        float pA = __expf(sumA), pB = __expf(sumB);
        denom += pA + pB;
#pragma unroll
        for (int k = 0; k < 8; k++)
            acc[k] = fmaf(vA[k], pA, fmaf(vB[k], pB, acc[k]));
    }
    // remainder: 1-3 edges, one pair at a time; duplicate edge zeroed
    for (; j < je; j += 2) {
        int ok1 = (j + 1 < je);
        int s = g_csrs[(half && ok1) ? j + 1 : j];
        float v[8];
        float sum = edge_dot8(g_xl_h, (size_t)s * HC + h * C_, sub, xr8, a8, v);
#pragma unroll
        for (int o = 8; o > 0; o >>= 1) sum += __shfl_xor_sync(0xffffffffu, sum, o);
        float p = __expf(sum);
        if (half && !ok1) p = 0.f;   // duplicate of edge j -> drop
        denom += p;
#pragma unroll
        for (int k = 0; k < 8; k++) acc[k] = fmaf(v[k], p, acc[k]);
    }

    // merge lane halves (each half has partial sums over its edges)
    denom += __shfl_xor_sync(0xffffffffu, denom, 16);
#pragma unroll
    for (int k = 0; k < 8; k++) acc[k] += __shfl_xor_sync(0xffffffffu, acc[k], 16);
    float inv = 1.f / denom;
#pragma unroll
    for (int k = 0; k < 8; k++) acc[k] *= inv;

    __shared__ float sh[4][128];
    __shared__ float ws[4], wq[4];
    if (half == 0) {
#pragma unroll
        for (int k = 0; k < 8; k++) sh[h][sub * 8 + k] = acc[k];
    }
    __syncthreads();

    int c = threadIdx.x;          // channel
    float m = 0.25f * (sh[0][c] + sh[1][c] + sh[2][c] + sh[3][c]) + cb[c];
    float t = m, tq = m * m;
#pragma unroll
    for (int o = 16; o > 0; o >>= 1) {
        t  += __shfl_xor_sync(0xffffffffu, t, o);
        tq += __shfl_xor_sync(0xffffffffu, tq, o);
    }
    if (lane == 0) { ws[h] = t; wq[h] = tq; }
    __syncthreads();
    float tot = ws[0] + ws[1] + ws[2] + ws[3];
    float tsq = wq[0] + wq[1] + wq[2] + wq[3];
    float mu = tot * (1.f / 128.f);
    float var = tsq * (1.f / 128.f) - mu * mu;
    float rstd = rsqrtf(var + EPS_);
    float o = fmaxf((m - mu) * rstd * gam[c] + bet[c], 0.f);
    float hn = g_h[(size_t)n * 128 + c] + o;
    g_h[(size_t)n * 128 + c] = hn;
    g_h16[(size_t)n * 128 + c] = __float2half_rn(hn);
}

// -------- global mean pool per graph (batch sorted -> contiguous ranges) -----
__global__ void pool_kernel(int N) {
    int b = blockIdx.x;
    int c = threadIdx.x;
    int lo = 0, hi = N;
    while (lo < hi) { int mid = (lo + hi) >> 1; if (g_batch[mid] < b) lo = mid + 1; else hi = mid; }
    int start = lo;
    lo = start; hi = N;
    while (lo < hi) { int mid = (lo + hi) >> 1; if (g_batch[mid] < b + 1) lo = mid + 1; else hi = mid; }
    int end = lo;
    float s = 0.f;
    for (int n = start; n < end; n++) s += g_h[(size_t)n * 128 + c];
    float cnt = (float)(end - start);
    g_pool[b * 128 + c] = s / fmaxf(cnt, 1.f);
}

// -------- MLP head: gelu(g W1^T + b1) W2^T + b2 -> layernorm -> out ----------
__global__ __launch_bounds__(256) void head_kernel(
    const float* __restrict__ W1, const float* __restrict__ b1,
    const float* __restrict__ W2, const float* __restrict__ b2,
    const float* __restrict__ og, const float* __restrict__ ob,
    float* __restrict__ out)
{
    int b = blockIdx.x;
    int tid = threadIdx.x;
    __shared__ float gv[128];
    __shared__ float hid[256];
    __shared__ float ov[128];
    __shared__ float red[256];
    if (tid < 128) gv[tid] = g_pool[b * 128 + tid];
    __syncthreads();
    {
        float s = b1[tid];
        const float* w = W1 + (size_t)tid * 128;
#pragma unroll 8
        for (int d = 0; d < 128; d++) s = fmaf(w[d], gv[d], s);
        hid[tid] = 0.5f * s * (1.f + erff(s * 0.70710678118654752f));
    }
    __syncthreads();
    if (tid < 128) {
        float s = b2[tid];
        const float* w = W2 + (size_t)tid * 256;
#pragma unroll 8
        for (int d = 0; d < 256; d++) s = fmaf(w[d], hid[d], s);
        ov[tid] = s;
    }
    __syncthreads();
    red[tid] = (tid < 128) ? ov[tid] : 0.f;
    __syncthreads();
    for (int o = 128; o > 0; o >>= 1) { if (tid < o) red[tid] += red[tid + o]; __syncthreads(); }
    float mu = red[0] * (1.f / 128.f);
    __syncthreads();
    red[tid] = (tid < 128) ? (ov[tid] - mu) * (ov[tid] - mu) : 0.f;
    __syncthreads();
    for (int o = 128; o > 0; o >>= 1) { if (tid < o) red[tid] += red[tid + o]; __syncthreads(); }
    float var = red[0] * (1.f / 128.f);
    if (tid < 128)
        out[b * 128 + tid] = (ov[tid] - mu) * rsqrtf(var + EPS_) * og[tid] + ob[tid];
}

// ---------------- launcher ----------------
extern "C" void kernel_launch(void* const* d_in, const int* in_sizes, int n_in,
                              void* d_out, int out_size) {
    const float* x     = (const float*)d_in[0];
    const int*   ei    = (const int*)d_in[1];
    const int*   batch = (const int*)d_in[2];
    const float* Wl    = (const float*)d_in[3];
    const float* bl    = (const float*)d_in[4];
    const float* Wr    = (const float*)d_in[5];
    const float* br    = (const float*)d_in[6];
    const float* att   = (const float*)d_in[7];
    const float* cb    = (const float*)d_in[8];
    const float* lng   = (const float*)d_in[9];
    const float* lnb   = (const float*)d_in[10];
    const float* W1    = (const float*)d_in[11];
    const float* b1    = (const float*)d_in[12];
    const float* W2    = (const float*)d_in[13];
    const float* b2    = (const float*)d_in[14];
    const float* og    = (const float*)d_in[15];
    const float* ob    = (const float*)d_in[16];
    float* out = (float*)d_out;

    // size-convention detection (validated: element counts)
    int scale = (out_size >= 4 * B_ * C_) ? 4 : 1;
    int sz0 = in_sizes[0] / scale;
    int sz1 = in_sizes[1] / scale;
    int sz2 = in_sizes[2] / scale;
    int N = sz0 / D_;
    int force = -1;
    int E;
    if (sz2 == 2 * N) { force = 0; E = sz1 / 4; }
    else              {            E = sz1 / 2; }
    if (N > NMAX) N = NMAX;
    if (E > EMAX) E = EMAX;
    int T = E + N;

    auto cdiv = [](int a, int b) { return (a + b - 1) / b; };

    // prep + CSR build
    zero_flags_deg<<<cdiv(N, 256), 256>>>(N);
    if (force < 0) {
        sniff_kernel<<<cdiv(E, 256), 256>>>(ei, E, 0);
        sniff_kernel<<<cdiv(N / 2, 256), 256>>>(batch, N / 2, 1);
    }
    convert_edges<<<cdiv(E, 256), 256>>>(ei, E, N, force);
    fill_selfloops<<<cdiv(N, 256), 256>>>(N, E);
    convert_batch<<<cdiv(N, 256), 256>>>(batch, N, force);
    copy_x<<<cdiv(N * 32, 256), 256>>>((const float4*)x, N * 32);
    scan_kernel<<<1, 1024>>>(N);
    scatter_csr<<<cdiv(T, 256), 256>>>(T);

    dim3 ggrid(8, cdiv(N, 128), 2);
    for (int l = 0; l < 3; l++) {
        size_t wo = (size_t)l * HC * D_;
        gemm_tc<<<ggrid, 256>>>(Wl + wo, bl + (size_t)l * HC,
                                Wr + wo, br + (size_t)l * HC, N);
        gat_layer<<<N, 128>>>(att + (size_t)l * HC, cb + (size_t)l * C_,
                              lng + (size_t)l * C_, lnb + (size_t)l * C_, N);
    }

    pool_kernel<<<B_, 128>>>(N);
    head_kernel<<<B_, 256>>>(W1, b1, W2, b2, og, ob, out);

    // diagnostics on non-captured calls only
    cudaStreamCaptureStatus cap = cudaStreamCaptureStatusNone;
    cudaStreamIsCapturing((cudaStream_t)0, &cap);
    if (cap == cudaStreamCaptureStatusNone) {
        float hout[4];
        cudaMemcpy(hout, out, sizeof(hout), cudaMemcpyDeviceToHost);
        fprintf(stderr, "HXDIAG N=%d E=%d force=%d out=%.4f,%.4f,%.4f,%.4f\n",
                N, E, force, hout[0], hout[1], hout[2], hout[3]);
    }
}

// round 16
// speedup vs baseline: 1.0745x; 1.0745x over previous
#include <cuda_runtime.h>
#include <cuda_fp16.h>
#include <math.h>
#include <stdio.h>

// ---------------- problem constants ----------------
constexpr int D_   = 128;   // in dim
constexpr int H_   = 4;     // heads
constexpr int C_   = 128;   // channels per head
constexpr int HC   = 512;   // H*C
constexpr int B_   = 64;    // graphs
constexpr int NMAX = 50000;
constexpr int EMAX = 400000;
constexpr int TMAX = NMAX + EMAX;  // edges + self loops
constexpr float NEG_SLOPE = 0.2f;
constexpr float EPS_ = 1e-5f;

// ---------------- scratch (static device globals; no allocation) -------------
// Referenced ONLY from device code (GB300 ATS silently accepts host-shadow
// addresses passed as kernel args — round-4 bug).
__device__ float  g_h   [(size_t)NMAX * D_];      // fp32 residual stream
__device__ __half g_h16 [(size_t)NMAX * D_];      // fp16 mirror (GEMM A input)
__device__ __half g_xl_h[(size_t)NMAX * HC];      // fp16 projections (L2-resident)
__device__ __half g_xr_h[(size_t)NMAX * HC];
__device__ int    g_src[TMAX];
__device__ int    g_dst[TMAX];
__device__ int    g_deg[NMAX];
__device__ int    g_rowptr[NMAX + 1];
__device__ int    g_cursor[NMAX];
__device__ int    g_csrs[TMAX];                   // CSR: src id per slot
__device__ int    g_batch[NMAX];
__device__ int    g_flag[2];
__device__ float  g_pool[B_ * C_];

// ---------------- small utility kernels ----------------
__global__ void zero_flags_deg(int N) {
    int i = blockIdx.x * blockDim.x + threadIdx.x;
    if (i < 2) g_flag[i] = 0;
    if (i < N) g_deg[i] = 0;
}
__global__ void sniff_kernel(const int* __restrict__ buf, int npairs, int which) {
    int i = blockIdx.x * blockDim.x + threadIdx.x;
    if (i < npairs && buf[2 * i + 1] != 0) g_flag[which] = 1;
}
__device__ __forceinline__ int clampi(int v, int lo, int hi) {
    return v < lo ? lo : (v > hi ? hi : v);
}
// converts edges AND counts in-degrees
__global__ void convert_edges(const int* __restrict__ buf, int E, int N, int forced) {
    int i = blockIdx.x * blockDim.x + threadIdx.x;
    if (i >= E) return;
    int is32 = (forced >= 0) ? forced : g_flag[0];
    int s, d;
    if (is32) { s = buf[i];     d = buf[E + i]; }
    else      { s = buf[2 * i]; d = buf[2 * (E + i)]; }
    s = clampi(s, 0, N - 1);
    d = clampi(d, 0, N - 1);
    g_src[i] = s;
    g_dst[i] = d;
    atomicAdd(&g_deg[d], 1);
}
__global__ void fill_selfloops(int N, int E) {
    int i = blockIdx.x * blockDim.x + threadIdx.x;
    if (i >= N) return;
    g_src[E + i] = i;
    g_dst[E + i] = i;
    g_deg[i] += 1;
}
__global__ void convert_batch(const int* __restrict__ buf, int N, int forced) {
    int i = blockIdx.x * blockDim.x + threadIdx.x;
    if (i >= N) return;
    int is32 = (forced >= 0) ? forced : g_flag[1];
    int b = is32 ? buf[i] : buf[2 * i];
    g_batch[i] = clampi(b, 0, B_ - 1);
}
// copies x into g_h (fp32) and g_h16 (fp16)
__global__ void copy_x(const float4* __restrict__ x4, int n4) {
    int i = blockIdx.x * blockDim.x + threadIdx.x;
    if (i >= n4) return;
    float4 v = x4[i];
    ((float4*)g_h)[i] = v;
    __half2 h0 = __floats2half2_rn(v.x, v.y);
    __half2 h1 = __floats2half2_rn(v.z, v.w);
    ((uint2*)g_h16)[i] = make_uint2(*(unsigned*)&h0, *(unsigned*)&h1);
}
__global__ void scan_kernel(int N) {
    __shared__ int sh[1024];
    __shared__ int carry_s;
    int tid = threadIdx.x;
    if (tid == 0) carry_s = 0;
    __syncthreads();
    for (int base = 0; base < N; base += 1024) {
        int v = (base + tid < N) ? g_deg[base + tid] : 0;
        sh[tid] = v;
        __syncthreads();
        for (int off = 1; off < 1024; off <<= 1) {
            int t = (tid >= off) ? sh[tid - off] : 0;
            __syncthreads();
            sh[tid] += t;
            __syncthreads();
        }
        int excl = sh[tid] - v + carry_s;
        if (base + tid < N) { g_rowptr[base + tid] = excl; g_cursor[base + tid] = excl; }
        __syncthreads();
        if (tid == 0) carry_s += sh[1023];
        __syncthreads();
    }
    if (tid == 0) g_rowptr[N] = carry_s;
}
__global__ void scatter_csr(int T) {
    int i = blockIdx.x * blockDim.x + threadIdx.x;
    if (i >= T) return;
    int d = g_dst[i];
    int pos = atomicAdd(&g_cursor[d], 1);
    if (pos < TMAX) g_csrs[pos] = g_src[i];
}

// ---------------- tensor-core GEMM (fp16 m16n8k16, fp32 accum) --------------
// Fused xl+xr: blockIdx.z selects (Wl->g_xl_h) or (Wr->g_xr_h).
// Block tile: 128 nodes x 64 cols. K=128 in TWO chunks of 64 halves
// (= 32 uints per row, pitch 36 -> all indices < 36, conflict-free frags).
__device__ __forceinline__ void mma_f16(float* c, const unsigned* a,
                                        unsigned b0, unsigned b1) {
    asm volatile(
        "mma.sync.aligned.m16n8k16.row.col.f32.f16.f16.f32 "
        "{%0,%1,%2,%3}, {%4,%5,%6,%7}, {%8,%9}, {%0,%1,%2,%3};"
        : "+f"(c[0]), "+f"(c[1]), "+f"(c[2]), "+f"(c[3])
        : "r"(a[0]), "r"(a[1]), "r"(a[2]), "r"(a[3]), "r"(b0), "r"(b1));
}

__global__ __launch_bounds__(256) void gemm_tc(
    const float* __restrict__ Wl, const float* __restrict__ bl,
    const float* __restrict__ Wr, const float* __restrict__ br,
    int N)
{
    int which = blockIdx.z;
    const float* W    = which ? Wr : Wl;
    const float* bias = which ? br : bl;
    __half* out_h     = which ? g_xr_h : g_xl_h;
    const float4* W4 = (const float4*)W;

    __shared__ unsigned Asu[128 * 36];   // chunk: 128 rows x 32 uints(64 halves) + pad
    __shared__ unsigned Bsu[64 * 36];    // chunk: 64 rows x 32 uints(64 halves) + pad

    int tid  = threadIdx.x;
    int warp = tid >> 5;
    int lane = tid & 31;
    int g  = lane >> 2;
    int tg = lane & 3;
    int nb = blockIdx.x * 64;    // col base
    int mb = blockIdx.y * 128;   // node base

    float c[8][4];
#pragma unroll
    for (int i = 0; i < 8; i++)
#pragma unroll
        for (int j = 0; j < 4; j++) c[i][j] = 0.f;

    for (int kc = 0; kc < 128; kc += 64) {
        // A chunk: 128 rows x 8 uint4 (64 halves per row)
#pragma unroll
        for (int it = 0; it < 4; it++) {
            int idx = tid + it * 256;            // 0..1023
            int row = idx >> 3, c4 = idx & 7;    // c4: 0..7
            int rg = mb + row; if (rg > N - 1) rg = N - 1;
            uint4 u = ((const uint4*)(g_h16 + (size_t)rg * 128 + kc))[c4];
            *(uint4*)&Asu[row * 36 + c4 * 4] = u;   // max 31 < 36
        }
        // W chunk: 64 rows x 16 float4 (64 floats per row), fp32 -> fp16
#pragma unroll
        for (int it = 0; it < 4; it++) {
            int idx = tid + it * 256;            // 0..1023
            int row = idx >> 4, c4 = idx & 15;   // c4: 0..15
            float4 f = W4[(size_t)(nb + row) * 32 + kc / 4 + c4];
            __half2 h0 = __floats2half2_rn(f.x, f.y);
            __half2 h1 = __floats2half2_rn(f.z, f.w);
            *(uint2*)&Bsu[row * 36 + c4 * 2] =      // max 31 < 36
                make_uint2(*(unsigned*)&h0, *(unsigned*)&h1);
        }
        __syncthreads();
#pragma unroll
        for (int ks = 0; ks < 4; ks++) {
            int kh = ks * 8;                     // uint offset within chunk row
            unsigned a[4];
            a[0] = Asu[(16 * warp + g) * 36 + kh + tg];
            a[1] = Asu[(16 * warp + g + 8) * 36 + kh + tg];
            a[2] = Asu[(16 * warp + g) * 36 + kh + tg + 4];
            a[3] = Asu[(16 * warp + g + 8) * 36 + kh + tg + 4];
#pragma unroll
            for (int nf = 0; nf < 8; nf++) {
                unsigned b0 = Bsu[(nf * 8 + g) * 36 + kh + tg];
                unsigned b1 = Bsu[(nf * 8 + g) * 36 + kh + tg + 4];
                mma_f16(c[nf], a, b0, b1);
            }
        }
        __syncthreads();
    }

    int node0 = mb + 16 * warp + g;
    int node1 = node0 + 8;
#pragma unroll
    for (int nf = 0; nf < 8; nf++) {
        int col = nb + nf * 8 + 2 * tg;
        float bv0 = __ldg(bias + col), bv1 = __ldg(bias + col + 1);
        if (node0 < N)
            *(__half2*)(out_h + (size_t)node0 * HC + col) =
                __floats2half2_rn(c[nf][0] + bv0, c[nf][1] + bv1);
        if (node1 < N)
            *(__half2*)(out_h + (size_t)node1 * HC + col) =
                __floats2half2_rn(c[nf][2] + bv0, c[nf][3] + bv1);
    }
}

// ---------- fused GAT layer: softmax + aggregate + head-mean/LN/residual -----
// Block = node (128 threads), warp = head. Single CSR pass, 4-edge unrolled so
// the 4 gathers and 4 shfl-reduction chains overlap (latency hiding).
// (Round-14 proven layout: one edge row per warp instruction, uint2/lane.)
__device__ __forceinline__ float lrelu(float x) { return x > 0.f ? x : NEG_SLOPE * x; }

__global__ __launch_bounds__(128) void gat_layer(
    const float* __restrict__ att_l, const float* __restrict__ cb,
    const float* __restrict__ gam, const float* __restrict__ bet, int N)
{
    int n = blockIdx.x;
    int h = threadIdx.x >> 5;
    int lane = threadIdx.x & 31;

    uint2 uxr = ((const uint2*)(g_xr_h + (size_t)n * HC + h * C_))[lane];
    float2 xr0 = __half22float2(*(__half2*)&uxr.x);
    float2 xr1 = __half22float2(*(__half2*)&uxr.y);
    float4 a = ((const float4*)(att_l + h * C_))[lane];

    int jb = g_rowptr[n], je = g_rowptr[n + 1];

    float denom = 0.f;
    float4 acc = make_float4(0.f, 0.f, 0.f, 0.f);

    int j = jb;
    for (; j + 4 <= je; j += 4) {
        int s0 = g_csrs[j], s1 = g_csrs[j + 1], s2 = g_csrs[j + 2], s3 = g_csrs[j + 3];
        uint2 u0 = ((const uint2*)(g_xl_h + (size_t)s0 * HC + h * C_))[lane];
        uint2 u1 = ((const uint2*)(g_xl_h + (size_t)s1 * HC + h * C_))[lane];
        uint2 u2 = ((const uint2*)(g_xl_h + (size_t)s2 * HC + h * C_))[lane];
        uint2 u3 = ((const uint2*)(g_xl_h + (size_t)s3 * HC + h * C_))[lane];
        float2 v00 = __half22float2(*(__half2*)&u0.x), v01 = __half22float2(*(__half2*)&u0.y);
        float2 v10 = __half22float2(*(__half2*)&u1.x), v11 = __half22float2(*(__half2*)&u1.y);
        float2 v20 = __half22float2(*(__half2*)&u2.x), v21 = __half22float2(*(__half2*)&u2.y);
        float2 v30 = __half22float2(*(__half2*)&u3.x), v31 = __half22float2(*(__half2*)&u3.y);
        float s0f = lrelu(v00.x + xr0.x) * a.x + lrelu(v00.y + xr0.y) * a.y +
                    lrelu(v01.x + xr1.x) * a.z + lrelu(v01.y + xr1.y) * a.w;
        float s1f = lrelu(v10.x + xr0.x) * a.x + lrelu(v10.y + xr0.y) * a.y +
                    lrelu(v11.x + xr1.x) * a.z + lrelu(v11.y + xr1.y) * a.w;
        float s2f = lrelu(v20.x + xr0.x) * a.x + lrelu(v20.y + xr0.y) * a.y +
                    lrelu(v21.x + xr1.x) * a.z + lrelu(v21.y + xr1.y) * a.w;
        float s3f = lrelu(v30.x + xr0.x) * a.x + lrelu(v30.y + xr0.y) * a.y +
                    lrelu(v31.x + xr1.x) * a.z + lrelu(v31.y + xr1.y) * a.w;
#pragma unroll
        for (int o = 16; o > 0; o >>= 1) {
            s0f += __shfl_xor_sync(0xffffffffu, s0f, o);
            s1f += __shfl_xor_sync(0xffffffffu, s1f, o);
            s2f += __shfl_xor_sync(0xffffffffu, s2f, o);
            s3f += __shfl_xor_sync(0xffffffffu, s3f, o);
        }
        float p0 = __expf(s0f), p1 = __expf(s1f), p2 = __expf(s2f), p3 = __expf(s3f);
        denom += (p0 + p1) + (p2 + p3);
        acc.x = fmaf(v00.x, p0, fmaf(v10.x, p1, fmaf(v20.x, p2, fmaf(v30.x, p3, acc.x))));
        acc.y = fmaf(v00.y, p0, fmaf(v10.y, p1, fmaf(v20.y, p2, fmaf(v30.y, p3, acc.y))));
        acc.z = fmaf(v01.x, p0, fmaf(v11.x, p1, fmaf(v21.x, p2, fmaf(v31.x, p3, acc.z))));
        acc.w = fmaf(v01.y, p0, fmaf(v11.y, p1, fmaf(v21.y, p2, fmaf(v31.y, p3, acc.w))));
    }
    for (; j < je; j++) {
        int s = g_csrs[j];
        uint2 uv = ((const uint2*)(g_xl_h + (size_t)s * HC + h * C_))[lane];
        float2 v0 = __half22float2(*(__half2*)&uv.x);
        float2 v1 = __half22float2(*(__half2*)&uv.y);
        float sum = lrelu(v0.x + xr0.x) * a.x + lrelu(v0.y + xr0.y) * a.y +
                    lrelu(v1.x + xr1.x) * a.z + lrelu(v1.y + xr1.y) * a.w;
#pragma unroll
        for (int o = 16; o > 0; o >>= 1) sum += __shfl_xor_sync(0xffffffffu, sum, o);
        float p = __expf(sum);
        denom += p;
        acc.x = fmaf(v0.x, p, acc.x);
        acc.y = fmaf(v0.y, p, acc.y);
        acc.z = fmaf(v1.x, p, acc.z);
        acc.w = fmaf(v1.y, p, acc.w);
    }
    float inv = 1.f / denom;
    acc.x *= inv; acc.y *= inv; acc.z *= inv; acc.w *= inv;

    __shared__ float sh[4][128];
    __shared__ float ws[4], wq[4];
    *(float4*)&sh[h][lane * 4] = acc;
    __syncthreads();

    int c = threadIdx.x;          // channel
    float m = 0.25f * (sh[0][c] + sh[1][c] + sh[2][c] + sh[3][c]) + cb[c];
    float t = m, tq = m * m;
#pragma unroll
    for (int o = 16; o > 0; o >>= 1) {
        t  += __shfl_xor_sync(0xffffffffu, t, o);
        tq += __shfl_xor_sync(0xffffffffu, tq, o);
    }
    if (lane == 0) { ws[h] = t; wq[h] = tq; }
    __syncthreads();
    float tot = ws[0] + ws[1] + ws[2] + ws[3];
    float tsq = wq[0] + wq[1] + wq[2] + wq[3];
    float mu = tot * (1.f / 128.f);
    float var = tsq * (1.f / 128.f) - mu * mu;
    float rstd = rsqrtf(var + EPS_);
    float o = fmaxf((m - mu) * rstd * gam[c] + bet[c], 0.f);
    float hn = g_h[(size_t)n * 128 + c] + o;
    g_h[(size_t)n * 128 + c] = hn;
    g_h16[(size_t)n * 128 + c] = __float2half_rn(hn);
}

// -------- global mean pool per graph (batch sorted -> contiguous ranges) -----
__global__ void pool_kernel(int N) {
    int b = blockIdx.x;
    int c = threadIdx.x;
    int lo = 0, hi = N;
    while (lo < hi) { int mid = (lo + hi) >> 1; if (g_batch[mid] < b) lo = mid + 1; else hi = mid; }
    int start = lo;
    lo = start; hi = N;
    while (lo < hi) { int mid = (lo + hi) >> 1; if (g_batch[mid] < b + 1) lo = mid + 1; else hi = mid; }
    int end = lo;
    float s = 0.f;
    for (int n = start; n < end; n++) s += g_h[(size_t)n * 128 + c];
    float cnt = (float)(end - start);
    g_pool[b * 128 + c] = s / fmaxf(cnt, 1.f);
}

// -------- MLP head: gelu(g W1^T + b1) W2^T + b2 -> layernorm -> out ----------
__global__ __launch_bounds__(256) void head_kernel(
    const float* __restrict__ W1, const float* __restrict__ b1,
    const float* __restrict__ W2, const float* __restrict__ b2,
    const float* __restrict__ og, const float* __restrict__ ob,
    float* __restrict__ out)
{
    int b = blockIdx.x;
    int tid = threadIdx.x;
    __shared__ float gv[128];
    __shared__ float hid[256];
    __shared__ float ov[128];
    __shared__ float red[256];
    if (tid < 128) gv[tid] = g_pool[b * 128 + tid];
    __syncthreads();
    {
        float s = b1[tid];
        const float* w = W1 + (size_t)tid * 128;
#pragma unroll 8
        for (int d = 0; d < 128; d++) s = fmaf(w[d], gv[d], s);
        hid[tid] = 0.5f * s * (1.f + erff(s * 0.70710678118654752f));
    }
    __syncthreads();
    if (tid < 128) {
        float s = b2[tid];
        const float* w = W2 + (size_t)tid * 256;
#pragma unroll 8
        for (int d = 0; d < 256; d++) s = fmaf(w[d], hid[d], s);
        ov[tid] = s;
    }
    __syncthreads();
    red[tid] = (tid < 128) ? ov[tid] : 0.f;
    __syncthreads();
    for (int o = 128; o > 0; o >>= 1) { if (tid < o) red[tid] += red[tid + o]; __syncthreads(); }
    float mu = red[0] * (1.f / 128.f);
    __syncthreads();
    red[tid] = (tid < 128) ? (ov[tid] - mu) * (ov[tid] - mu) : 0.f;
    __syncthreads();
    for (int o = 128; o > 0; o >>= 1) { if (tid < o) red[tid] += red[tid + o]; __syncthreads(); }
    float var = red[0] * (1.f / 128.f);
    if (tid < 128)
        out[b * 128 + tid] = (ov[tid] - mu) * rsqrtf(var + EPS_) * og[tid] + ob[tid];
}

// ---------------- launcher ----------------
extern "C" void kernel_launch(void* const* d_in, const int* in_sizes, int n_in,
                              void* d_out, int out_size) {
    const float* x     = (const float*)d_in[0];
    const int*   ei    = (const int*)d_in[1];
    const int*   batch = (const int*)d_in[2];
    const float* Wl    = (const float*)d_in[3];
    const float* bl    = (const float*)d_in[4];
    const float* Wr    = (const float*)d_in[5];
    const float* br    = (const float*)d_in[6];
    const float* att   = (const float*)d_in[7];
    const float* cb    = (const float*)d_in[8];
    const float* lng   = (const float*)d_in[9];
    const float* lnb   = (const float*)d_in[10];
    const float* W1    = (const float*)d_in[11];
    const float* b1    = (const float*)d_in[12];
    const float* W2    = (const float*)d_in[13];
    const float* b2    = (const float*)d_in[14];
    const float* og    = (const float*)d_in[15];
    const float* ob    = (const float*)d_in[16];
    float* out = (float*)d_out;

    // size-convention detection (validated: element counts)
    int scale = (out_size >= 4 * B_ * C_) ? 4 : 1;
    int sz0 = in_sizes[0] / scale;
    int sz1 = in_sizes[1] / scale;
    int sz2 = in_sizes[2] / scale;
    int N = sz0 / D_;
    int force = -1;
    int E;
    if (sz2 == 2 * N) { force = 0; E = sz1 / 4; }
    else              {            E = sz1 / 2; }
    if (N > NMAX) N = NMAX;
    if (E > EMAX) E = EMAX;
    int T = E + N;

    auto cdiv = [](int a, int b) { return (a + b - 1) / b; };

    // prep + CSR build
    zero_flags_deg<<<cdiv(N, 256), 256>>>(N);
    if (force < 0) {
        sniff_kernel<<<cdiv(E, 256), 256>>>(ei, E, 0);
        sniff_kernel<<<cdiv(N / 2, 256), 256>>>(batch, N / 2, 1);
    }
    convert_edges<<<cdiv(E, 256), 256>>>(ei, E, N, force);
    fill_selfloops<<<cdiv(N, 256), 256>>>(N, E);
    convert_batch<<<cdiv(N, 256), 256>>>(batch, N, force);
    copy_x<<<cdiv(N * 32, 256), 256>>>((const float4*)x, N * 32);
    scan_kernel<<<1, 1024>>>(N);
    scatter_csr<<<cdiv(T, 256), 256>>>(T);

    dim3 ggrid(8, cdiv(N, 128), 2);
    for (int l = 0; l < 3; l++) {
        size_t wo = (size_t)l * HC * D_;
        gemm_tc<<<ggrid, 256>>>(Wl + wo, bl + (size_t)l * HC,
                                Wr + wo, br + (size_t)l * HC, N);
        gat_layer<<<N, 128>>>(att + (size_t)l * HC, cb + (size_t)l * C_,
                              lng + (size_t)l * C_, lnb + (size_t)l * C_, N);
    }

    pool_kernel<<<B_, 128>>>(N);
    head_kernel<<<B_, 256>>>(W1, b1, W2, b2, og, ob, out);

    // diagnostics on non-captured calls only
    cudaStreamCaptureStatus cap = cudaStreamCaptureStatusNone;
    cudaStreamIsCapturing((cudaStream_t)0, &cap);
    if (cap == cudaStreamCaptureStatusNone) {
        float hout[4];
        cudaMemcpy(hout, out, sizeof(hout), cudaMemcpyDeviceToHost);
        fprintf(stderr, "HXDIAG N=%d E=%d force=%d out=%.4f,%.4f,%.4f,%.4f\n",
                N, E, force, hout[0], hout[1], hout[2], hout[3]);
    }
}